// round 3
// baseline (speedup 1.0000x reference)
#include <cuda_runtime.h>
#include <math.h>

// Problem constants
#define NB 64
#define ND 256
#define NT 1024
#define NC 1024
#define NROWS (NB*NT)          // 65536
#define Q_SZ (NB*ND*NT)        // 16777216

// Output layout (flattened tuple, all float32):
// [0, Q_SZ)            quantized_out [B, D, T]
// [Q_SZ]               loss
// [Q_SZ+1]             cmt_loss
// [Q_SZ+2, +NROWS)     encoding_indices [B, T, 1] (as float)
// [Q_SZ+2+NROWS]       perplexity
#define LOSS_OFF Q_SZ
#define CMT_OFF  (Q_SZ+1)
#define IDX_OFF  (Q_SZ+2)
#define PERP_OFF (Q_SZ+2+NROWS)

// Scratch (no allocations allowed -> device globals)
__device__ float g_enorm[NC];
__device__ int   g_idx[NROWS];
__device__ float g_mindist[NROWS];
__device__ int   g_counts[NC];

// Monotonic float<->uint mapping for order-independent atomicMax argmax
__device__ __forceinline__ unsigned ford(float f){
    unsigned u = __float_as_uint(f);
    return (u & 0x80000000u) ? ~u : (u | 0x80000000u);
}
__device__ __forceinline__ float fdec(unsigned u){
    return __uint_as_float((u & 0x80000000u) ? (u & 0x7FFFFFFFu) : ~u);
}

// ---------------------------------------------------------------------------
// Kernel 1: per-code squared norms + zero the histogram
// ---------------------------------------------------------------------------
__global__ void vq_prep(const float* __restrict__ E){
    int j = blockIdx.x;
    int lane = threadIdx.x;
    float s = 0.f;
    #pragma unroll
    for (int d = lane; d < ND; d += 32){
        float v = E[j*ND + d];
        s += v*v;
    }
    #pragma unroll
    for (int o = 16; o; o >>= 1) s += __shfl_down_sync(0xffffffffu, s, o);
    if (lane == 0){
        g_enorm[j]  = s;
        g_counts[j] = 0;
    }
}

// ---------------------------------------------------------------------------
// Kernel 2: main distance-argmin GEMM.
// X is [B, D, T] so for a fixed b the tile X_b is [K=256, T=1024] with t
// contiguous -> classic SGEMM tiling: block handles (b, 128 t-values),
// streams all 1024 codes in 8 tiles of 128, micro-tile 8 codes x 8 t per
// thread (256 threads = 16x16). Running per-t argmax kept in shared u64
// via atomicMax (deterministic; tie -> lowest index).
// Also accumulates ||x_t||^2 on the first code-tile pass (X tile is resident
// in smem anyway), avoiding a separate 64MB read.
// ---------------------------------------------------------------------------
__global__ void __launch_bounds__(256,2) vq_main(const float* __restrict__ X,
                                                 const float* __restrict__ E,
                                                 float* __restrict__ out){
    __shared__ float sE[16][132];   // [k][code], padded (132%4==0 keeps f4 align)
    __shared__ float sX[16][128];   // [k][t]
    __shared__ unsigned long long sBest[128];

    const int tid = threadIdx.x;
    const int b  = blockIdx.y;
    const int t0 = blockIdx.x * 128;
    const int tx = tid & 15;    // t micro-group   (8 t each)
    const int ty = tid >> 4;    // code micro-group (8 codes each)

    if (tid < 128) sBest[tid] = 0ull;
    float xnorm = 0.f;
    const float* Xb = X + (size_t)b * ND * NT;

    for (int jt = 0; jt < 8; jt++){
        const int jbase = jt * 128;
        float acc[8][8];
        #pragma unroll
        for (int i = 0; i < 8; i++)
            #pragma unroll
            for (int j = 0; j < 8; j++) acc[i][j] = 0.f;

        for (int k0 = 0; k0 < 256; k0 += 16){
            __syncthreads();  // previous tile fully consumed
            // E tile: each thread loads 2 float4 (row j=tid/4 (+64), 4 k's)
            {
                int j = tid >> 2, g = tid & 3;
                #pragma unroll
                for (int r = 0; r < 2; r++){
                    int jj = j + r*64;
                    float4 v = *(const float4*)&E[(jbase + jj)*ND + k0 + g*4];
                    sE[g*4+0][jj] = v.x; sE[g*4+1][jj] = v.y;
                    sE[g*4+2][jj] = v.z; sE[g*4+3][jj] = v.w;
                }
            }
            // X tile: coalesced float4 copy, row kk=tid/32 (+8)
            {
                int kk = tid >> 5, c = tid & 31;
                #pragma unroll
                for (int r = 0; r < 2; r++){
                    int kr = kk + r*8;
                    float4 v = *(const float4*)&Xb[(size_t)(k0 + kr)*NT + t0 + c*4];
                    *(float4*)&sX[kr][c*4] = v;
                }
            }
            __syncthreads();

            // ||x||^2 accumulation (only once, while tiles are resident)
            if (jt == 0 && tid < 128){
                #pragma unroll
                for (int kk = 0; kk < 16; kk++){
                    float v = sX[kk][tid];
                    xnorm += v*v;
                }
            }

            #pragma unroll
            for (int kk = 0; kk < 16; kk++){
                float4 e0 = *(const float4*)&sE[kk][ty*8];
                float4 e1 = *(const float4*)&sE[kk][ty*8+4];
                float4 x0 = *(const float4*)&sX[kk][tx*8];
                float4 x1 = *(const float4*)&sX[kk][tx*8+4];
                float ev[8] = {e0.x,e0.y,e0.z,e0.w,e1.x,e1.y,e1.z,e1.w};
                float xv[8] = {x0.x,x0.y,x0.z,x0.w,x1.x,x1.y,x1.z,x1.w};
                #pragma unroll
                for (int i = 0; i < 8; i++)
                    #pragma unroll
                    for (int j = 0; j < 8; j++)
                        acc[i][j] = fmaf(ev[i], xv[j], acc[i][j]);
            }
        }

        // fold this 128-code tile into running per-t best
        #pragma unroll
        for (int j = 0; j < 8; j++){
            float best = -3.4e38f; int bi = 0;
            #pragma unroll
            for (int i = 0; i < 8; i++){
                int code = jbase + ty*8 + i;
                float s = 2.f*acc[i][j] - g_enorm[code];
                if (s > best){ best = s; bi = code; }   // strict > : lowest index wins
            }
            unsigned long long p =
                ((unsigned long long)ford(best) << 32) | (unsigned)(0xFFFFFFFFu - bi);
            atomicMax(&sBest[tx*8 + j], p);
        }
    }
    __syncthreads();

    if (tid < 128){
        unsigned long long p = sBest[tid];
        int   idx = (int)(0xFFFFFFFFu - (unsigned)(p & 0xFFFFFFFFu));
        float sc  = fdec((unsigned)(p >> 32));
        int row = b*NT + t0 + tid;
        g_idx[row]     = idx;
        g_mindist[row] = xnorm - sc;          // ||x||^2 - (2 x.e - ||e||^2)
        atomicAdd(&g_counts[idx], 1);         // integer -> deterministic
        out[IDX_OFF + row] = (float)idx;
    }
}

// ---------------------------------------------------------------------------
// Kernel 3: quantized_out[b, d, t] = embed[idx[b,t], d]  (coalesced in t)
// ---------------------------------------------------------------------------
__global__ void __launch_bounds__(256) vq_gather(const float* __restrict__ E,
                                                 float* __restrict__ out){
    int b  = blockIdx.y;
    int t0 = blockIdx.x * 128;
    int t    = threadIdx.x & 127;
    int half = threadIdx.x >> 7;
    int idx = g_idx[b*NT + t0 + t];
    const float* er = E + (size_t)idx * ND;
    float* op = out + (size_t)b * ND * NT + t0 + t;
    #pragma unroll 4
    for (int d = half; d < ND; d += 2)
        op[(size_t)d * NT] = er[d];
}

// ---------------------------------------------------------------------------
// Kernel 4: scalars. mse = sum(mindist)/(N*D); loss = 1.2*mse (codebook and
// commitment losses are numerically identical); perplexity from histogram.
// Fixed-tree double reductions -> deterministic.
// ---------------------------------------------------------------------------
__global__ void vq_finalize(float* __restrict__ out){
    __shared__ double sh[1024];
    int tid = threadIdx.x;

    double loc = 0.0;
    for (int r = tid; r < NROWS; r += 1024) loc += (double)g_mindist[r];
    sh[tid] = loc; __syncthreads();
    for (int s = 512; s > 0; s >>= 1){
        if (tid < s) sh[tid] += sh[tid + s];
        __syncthreads();
    }
    double mse = sh[0] / (double)Q_SZ;
    __syncthreads();

    double p = (double)g_counts[tid] / (double)NROWS;
    sh[tid] = -p * log(p + 1e-10);
    __syncthreads();
    for (int s = 512; s > 0; s >>= 1){
        if (tid < s) sh[tid] += sh[tid + s];
        __syncthreads();
    }
    if (tid == 0){
        float m = (float)mse;
        out[LOSS_OFF] = m + 0.2f * m;
        out[CMT_OFF]  = m;
        out[PERP_OFF] = (float)exp(sh[0]);
    }
}

// ---------------------------------------------------------------------------
extern "C" void kernel_launch(void* const* d_in, const int* in_sizes, int n_in,
                              void* d_out, int out_size){
    const float* X = (const float*)d_in[0];  // [B, D, T] fp32
    const float* E = (const float*)d_in[1];  // [NC, D] fp32
    float* out = (float*)d_out;
    (void)in_sizes; (void)n_in; (void)out_size;

    vq_prep    <<<NC, 32>>>(E);
    vq_main    <<<dim3(8, NB), 256>>>(X, E, out);
    vq_gather  <<<dim3(8, NB), 256>>>(E, out);
    vq_finalize<<<1, 1024>>>(out);
}